// round 5
// baseline (speedup 1.0000x reference)
#include <cuda_runtime.h>
#include <cstddef>

// GraphSage gather + cosine top-16 + mean.  (Round 5)
//   d_in[0] nodes  : int32 [N]
//   d_in[1] neigh  : int32 [N, 32]
//   d_in[2] u2e_visual : f32 [500000, 64]
//   d_in[3] u2e_text   : f32 [500000, 64]
// Output: f32 concat(u_v, u_t, v_agg, t_agg), each [N, 64].
//
// One warp per (node, modality), modality-major order (single-table L2 phase).
// Sim loop: each 8-lane group owns 8 contiguous neighbors, accumulates 8
// (dot, nsq) partial pairs in registers, then ONE 14-shfl exchange tree
// reduces all 16 values (vs 48 shfls for per-neighbor butterflies) and lands
// sim(k) directly on lane k. Ranking via dot*|dot|/||v||^2 (monotone, no
// sqrt), stable top-16 rank count, 16-lane mean of selected rows.

#define DEG   32
#define TOPK  16
#define EMB   64

__global__ __launch_bounds__(256, 6) void gs_kernel(
    const int*   __restrict__ nodes,
    const int*   __restrict__ neigh,
    const float* __restrict__ uv,
    const float* __restrict__ ut,
    float*       __restrict__ out,
    int n)
{
    const unsigned FULL = 0xffffffffu;
    int wg = (int)((blockIdx.x * blockDim.x + threadIdx.x) >> 5);
    if (wg >= 2 * n) return;
    int lane = threadIdx.x & 31;

    // modality-major task order: [0,n) = visual, [n,2n) = text
    int m    = (wg >= n) ? 1 : 0;
    int node = wg - m * n;
    const float* __restrict__ emb = m ? ut : uv;

    int g = lane >> 3;     // 8-lane group id (0..3): owns neighbors 8g..8g+7
    int s = lane & 7;      // sub-lane within group

    // ---- center gather (lane s holds float4 s and s+8 of the row) ----
    int cidx = __ldcs(nodes + node);
    const float4* crow = (const float4*)(emb + (size_t)cidx * EMB);
    float4 ua = __ldg(crow + s);
    float4 ub = __ldg(crow + s + 8);

    size_t nn = (size_t)n * EMB;
    float4* cout = (float4*)(out + (size_t)m * nn + (size_t)node * EMB);
    if (g == 0) { __stcs(cout + s, ua); __stcs(cout + s + 8, ub); }

    // ---- neighbor indices: lane k holds neigh[node][k] ----
    int nidx = __ldcs(neigh + (size_t)node * DEG + lane);

    // ---- per-group accumulation: 8 neighbors' (dot, nsq) partials ----
    float dt[8], nq[8];
    #pragma unroll
    for (int t = 0; t < 8; t++) {
        int j = __shfl_sync(FULL, nidx, 8 * g + t);   // variable-src shfl
        const float4* vrow = (const float4*)(emb + (size_t)j * EMB);
        float4 va = __ldg(vrow + s);
        float4 vb = __ldg(vrow + s + 8);
        dt[t] = va.x * ua.x + va.y * ua.y + va.z * ua.z + va.w * ua.w
              + vb.x * ub.x + vb.y * ub.y + vb.z * ub.z + vb.w * ub.w;
        nq[t] = va.x * va.x + va.y * va.y + va.z * va.z + va.w * va.w
              + vb.x * vb.x + vb.y * vb.y + vb.z * vb.z + vb.w * vb.w;
    }

    // ---- exchange tree: reduce 8 values across 8 lanes, 7 shfls per set.
    //      After stage sequence lane s holds the full sums for neighbor 8g+s.
    // stage d=4
    {
        bool hi = (s & 4) != 0;
        #pragma unroll
        for (int i = 0; i < 4; i++) {
            float sd = hi ? dt[i] : dt[i + 4];
            float sn = hi ? nq[i] : nq[i + 4];
            float rd = __shfl_xor_sync(FULL, sd, 4);
            float rn = __shfl_xor_sync(FULL, sn, 4);
            dt[i] = (hi ? dt[i + 4] : dt[i]) + rd;
            nq[i] = (hi ? nq[i + 4] : nq[i]) + rn;
        }
    }
    // stage d=2
    {
        bool hi = (s & 2) != 0;
        #pragma unroll
        for (int i = 0; i < 2; i++) {
            float sd = hi ? dt[i] : dt[i + 2];
            float sn = hi ? nq[i] : nq[i + 2];
            float rd = __shfl_xor_sync(FULL, sd, 2);
            float rn = __shfl_xor_sync(FULL, sn, 2);
            dt[i] = (hi ? dt[i + 2] : dt[i]) + rd;
            nq[i] = (hi ? nq[i + 2] : nq[i]) + rn;
        }
    }
    // stage d=1
    float dot, nsq;
    {
        bool hi = (s & 1) != 0;
        float sd = hi ? dt[0] : dt[1];
        float sn = hi ? nq[0] : nq[1];
        float rd = __shfl_xor_sync(FULL, sd, 1);
        float rn = __shfl_xor_sync(FULL, sn, 1);
        dot = (hi ? dt[1] : dt[0]) + rd;
        nsq = (hi ? nq[1] : nq[0]) + rn;
    }

    // lane L now holds (dot, nsq) of neighbor L.
    // ranking value: dot*|dot|/||v||^2 — strictly monotone in cosine
    // (center norm is a positive per-node constant, irrelevant to order).
    float mysim = __fdividef(dot * fabsf(dot), nsq + 1e-20f);

    // ---- stable top-16 via rank count (matches jax.lax.top_k tie-break) ----
    int cnt = 0;
    #pragma unroll
    for (int d = 1; d < DEG; d++) {
        float o = __shfl_xor_sync(FULL, mysim, d);
        int jl = lane ^ d;
        cnt += (o > mysim) || (o == mysim && jl < lane);
    }
    unsigned sel = __ballot_sync(FULL, cnt < TOPK);   // exactly TOPK bits set

    // ---- mean of selected (unnormalized) rows; re-reads mostly L1/L2-hit ----
    int half = lane >> 4;   // 16-lane halves: 2 neighbors per iteration
    int sub  = lane & 15;
    float4 acc = make_float4(0.f, 0.f, 0.f, 0.f);
    #pragma unroll
    for (int k = 0; k < DEG; k += 2) {
        int kk = k + half;
        int j = __shfl_sync(FULL, nidx, kk);
        if (sel & (1u << kk)) {
            float4 v = __ldg((const float4*)(emb + (size_t)j * EMB) + sub);
            acc.x += v.x; acc.y += v.y; acc.z += v.z; acc.w += v.w;
        }
    }
    acc.x += __shfl_xor_sync(FULL, acc.x, 16);
    acc.y += __shfl_xor_sync(FULL, acc.y, 16);
    acc.z += __shfl_xor_sync(FULL, acc.z, 16);
    acc.w += __shfl_xor_sync(FULL, acc.w, 16);

    if (half == 0) {
        const float sc = 1.0f / (float)TOPK;
        float4 r = make_float4(acc.x * sc, acc.y * sc, acc.z * sc, acc.w * sc);
        float4* aout = (float4*)(out + (size_t)(2 + m) * nn + (size_t)node * EMB);
        __stcs(aout + sub, r);
    }
}

extern "C" void kernel_launch(void* const* d_in, const int* in_sizes, int n_in,
                              void* d_out, int out_size) {
    const int*   nodes = (const int*)d_in[0];
    const int*   neigh = (const int*)d_in[1];
    const float* uv    = (const float*)d_in[2];
    const float* ut    = (const float*)d_in[3];
    float*       out   = (float*)d_out;
    int n = in_sizes[0];
    int warps = 2 * n;
    int threads = 256;
    int blocks = (warps * 32 + threads - 1) / threads;
    gs_kernel<<<blocks, threads>>>(nodes, neigh, uv, ut, out, n);
}